// round 14
// baseline (speedup 1.0000x reference)
#include <cuda_runtime.h>
#include <cstdint>

// Problem constants
#define D_MODEL 1024
#define NHEAD   16
#define HDIM    64
#define BB      2
#define LSEQ    2048
#define MROWS   (BB * LSEQ)   // 4096

// ---------------- scratch (device globals; no allocations allowed) ----------
__device__ float g_Q[MROWS * D_MODEL];   // head-major (B,H,L,HDIM), tf32-rounded
__device__ float g_K[MROWS * D_MODEL];
__device__ float g_V[MROWS * D_MODEL];
__device__ float g_C[MROWS * D_MODEL];   // attention context, head-major, tf32-rounded
__device__ float g_A[3 * MROWS * D_MODEL];    // tf32-rounded query/key/value
__device__ float g_Wr[4 * D_MODEL * D_MODEL]; // tf32-rounded Wq/Wk/Wv/Wo

// ---------------- helpers ---------------------------------------------------
__device__ __forceinline__ uint32_t f2tf(float x) {
    uint32_t r;
    asm("cvt.rna.tf32.f32 %0, %1;" : "=r"(r) : "f"(x));
    return r;
}
__device__ __forceinline__ float f2tff(float x) { return __uint_as_float(f2tf(x)); }

__device__ __forceinline__ void mma8(float* c, const uint32_t* a, const uint32_t* b) {
    asm volatile(
        "mma.sync.aligned.m16n8k8.row.col.f32.tf32.tf32.f32 "
        "{%0,%1,%2,%3},{%4,%5,%6,%7},{%8,%9},{%0,%1,%2,%3};\n"
        : "+f"(c[0]), "+f"(c[1]), "+f"(c[2]), "+f"(c[3])
        : "r"(a[0]), "r"(a[1]), "r"(a[2]), "r"(a[3]), "r"(b[0]), "r"(b[1]));
}

__device__ __forceinline__ void cpa16(void* dst, const void* src) {
    uint32_t d = (uint32_t)__cvta_generic_to_shared(dst);
    asm volatile("cp.async.cg.shared.global [%0], [%1], 16;" :: "r"(d), "l"(src));
}
__device__ __forceinline__ void cp_commit() {
    asm volatile("cp.async.commit_group;");
}
template<int N>
__device__ __forceinline__ void cp_wait() {
    asm volatile("cp.async.wait_group %0;" :: "n"(N));
}

// ---------------- pre-round pass: tf32-round inputs & weights once ----------
// Hoists the cvt.rna out of the GEMM inner loops (A rows are reused by 8
// n-blocks, W rows by 32 m-blocks). Bit-identical to converting per-fragment.
__global__ __launch_bounds__(256)
void round_pass(const float* __restrict__ q, const float* __restrict__ k,
                const float* __restrict__ v, const float* __restrict__ Wq,
                const float* __restrict__ Wk, const float* __restrict__ Wv,
                const float* __restrict__ Wo)
{
    const int z = blockIdx.y;
    const float* src;
    float* dst;
    int n4;
    if (z < 3) {
        src = (z == 0) ? q : (z == 1) ? k : v;
        dst = g_A + (size_t)z * MROWS * D_MODEL;
        n4  = MROWS * D_MODEL / 4;
    } else {
        int wsel = z - 3;
        src = (wsel == 0) ? Wq : (wsel == 1) ? Wk : (wsel == 2) ? Wv : Wo;
        dst = g_Wr + (size_t)wsel * D_MODEL * D_MODEL;
        n4  = D_MODEL * D_MODEL / 4;
    }
    int i = blockIdx.x * blockDim.x + threadIdx.x;
    if (i < n4) {
        float4 x = ((const float4*)src)[i];
        x.x = f2tff(x.x); x.y = f2tff(x.y);
        x.z = f2tff(x.z); x.w = f2tff(x.w);
        ((float4*)dst)[i] = x;
    }
}

// ---------------- TF32 GEMM body: C[M,N] = A[M,K] * W[N,K]^T (+bias) --------
// M=4096, N=K=1024. Block tile 128x128, BK=16, 256 threads = 8 warps, each
// warp owns a 64x32 tile. A and W are PRE-ROUNDED tf32 (round_pass / attn
// epilogue), so fragments load raw — no cvt in the inner loop. Staging is
// raw cp.async; 2 CTAs/SM for latency hiding.
#define GM   128
#define GN   128
#define GK   16
#define GLD  20     // padded row stride (floats)
#define GSTG 3
#define GA_TILE (GM * GLD)
#define GB_TILE (GN * GLD)

template<bool A_HEADED, bool OUT_HEADED, bool HAS_BIAS>
__device__ __forceinline__
void gemm_body(const float* __restrict__ A, const float* __restrict__ W,
               const float* __restrict__ bias, float* __restrict__ C)
{
    extern __shared__ float gsm[];
    float* As = gsm;                    // GSTG x GA_TILE
    float* Bs = gsm + GSTG * GA_TILE;   // GSTG x GB_TILE

    const int tid  = threadIdx.x;
    const int m0   = blockIdx.y * GM;
    const int n0   = blockIdx.x * GN;
    const int lane = tid & 31;
    const int wid  = tid >> 5;
    const int g    = lane >> 2;       // groupID
    const int t    = lane & 3;        // threadID_in_group
    const int wm   = (wid & 1) * 64;  // warp m offset (2-way)
    const int wn   = (wid >> 1) * 32; // warp n offset (4-way)

    auto a_ptr = [&](int m, int k) -> const float* {
        if (A_HEADED) {
            int b = m >> 11, l = m & (LSEQ - 1);
            int h = k >> 6,  d = k & (HDIM - 1);
            return A + (((size_t)(b * NHEAD + h) * LSEQ + l) * HDIM + d);
        } else {
            return A + (size_t)m * D_MODEL + k;
        }
    };

    // stage kt-th K-slab: A 128x16 (512 16B chunks) + B 128x16 (512 chunks)
    auto issue_tile = [&](int kt) {
        const int st = kt % GSTG;
        const int k0 = kt * GK;
        float* Ad = As + st * GA_TILE;
        float* Bd = Bs + st * GB_TILE;
        #pragma unroll
        for (int it = 0; it < 2; ++it) {
            int i = tid + it * 256;           // 0..511
            int r = i >> 2, c = (i & 3) * 4;
            cpa16(Ad + r * GLD + c, a_ptr(m0 + r, k0 + c));
        }
        #pragma unroll
        for (int it = 0; it < 2; ++it) {
            int i = tid + it * 256;           // 0..511
            int r = i >> 2, c = (i & 3) * 4;
            cpa16(Bd + r * GLD + c, W + (size_t)(n0 + r) * D_MODEL + k0 + c);
        }
        cp_commit();
    };

    float acc[4][4][4];
    #pragma unroll
    for (int i = 0; i < 4; i++)
        #pragma unroll
        for (int j = 0; j < 4; j++)
            #pragma unroll
            for (int e = 0; e < 4; e++) acc[i][j][e] = 0.f;

    const int NKT = D_MODEL / GK;   // 64
    issue_tile(0);
    issue_tile(1);

    for (int kt = 0; kt < NKT; ++kt) {
        if (kt + 1 < NKT) cp_wait<1>(); else cp_wait<0>();
        __syncthreads();
        if (kt + 2 < NKT) issue_tile(kt + 2);

        const int st = kt % GSTG;
        const float* Asb = As + st * GA_TILE;
        const float* Bsb = Bs + st * GB_TILE;

        #pragma unroll
        for (int kk = 0; kk < GK; kk += 8) {
            uint32_t af[4][4];
            #pragma unroll
            for (int mt = 0; mt < 4; mt++) {
                int r = wm + mt * 16 + g;
                af[mt][0] = __float_as_uint(Asb[r * GLD + kk + t]);
                af[mt][1] = __float_as_uint(Asb[(r + 8) * GLD + kk + t]);
                af[mt][2] = __float_as_uint(Asb[r * GLD + kk + t + 4]);
                af[mt][3] = __float_as_uint(Asb[(r + 8) * GLD + kk + t + 4]);
            }
            uint32_t bf[4][2];
            #pragma unroll
            for (int nt = 0; nt < 4; nt++) {
                int n = wn + nt * 8 + g;
                bf[nt][0] = __float_as_uint(Bsb[n * GLD + kk + t]);
                bf[nt][1] = __float_as_uint(Bsb[n * GLD + kk + t + 4]);
            }
            #pragma unroll
            for (int mt = 0; mt < 4; mt++)
                #pragma unroll
                for (int nt = 0; nt < 4; nt++)
                    mma8(acc[mt][nt], af[mt], bf[nt]);
        }
    }

    // epilogue
    #pragma unroll
    for (int mt = 0; mt < 4; mt++) {
        #pragma unroll
        for (int nt = 0; nt < 4; nt++) {
            int m = m0 + wm + mt * 16 + g;
            int n = n0 + wn + nt * 8 + 2 * t;
            float v0 = acc[mt][nt][0], v1 = acc[mt][nt][1];
            float v2 = acc[mt][nt][2], v3 = acc[mt][nt][3];
            if (HAS_BIAS) {
                float b0 = bias[n], b1 = bias[n + 1];
                v0 += b0; v1 += b1; v2 += b0; v3 += b1;
            }
            if (OUT_HEADED) {
                // round to tf32 here so attention can consume raw bytes
                v0 = f2tff(v0); v1 = f2tff(v1); v2 = f2tff(v2); v3 = f2tff(v3);
                int b = m >> 11, l = m & (LSEQ - 1);
                int h = n >> 6,  d = n & (HDIM - 1);
                size_t base = ((size_t)(b * NHEAD + h) * LSEQ + l) * HDIM + d;
                size_t base8 = base + 8 * HDIM;
                C[base]     = v0; C[base + 1]  = v1;
                C[base8]    = v2; C[base8 + 1] = v3;
            } else {
                C[(size_t)m * D_MODEL + n]           = v0;
                C[(size_t)m * D_MODEL + n + 1]       = v1;
                C[(size_t)(m + 8) * D_MODEL + n]     = v2;
                C[(size_t)(m + 8) * D_MODEL + n + 1] = v3;
            }
        }
    }
}

// fused QKV projections: blockIdx.z selects {query,key,value}
__global__ __launch_bounds__(256, 2)
void gemm_qkv(float* __restrict__ pQ, float* __restrict__ pK, float* __restrict__ pV)
{
    const int z = blockIdx.z;
    const float* A = g_A + (size_t)z * MROWS * D_MODEL;
    const float* W = g_Wr + (size_t)z * D_MODEL * D_MODEL;
    float*       C = (z == 0) ? pQ : (z == 1) ? pK : pV;
    gemm_body<false, true, false>(A, W, nullptr, C);
}

// output projection (A = g_C pre-rounded by attention epilogue, W = rounded Wo)
__global__ __launch_bounds__(256, 2)
void gemm_out(const float* __restrict__ A, const float* __restrict__ bias,
              float* __restrict__ C)
{
    gemm_body<true, false, true>(A, g_Wr + (size_t)3 * D_MODEL * D_MODEL, bias, C);
}

// ---------------- flash attention (TF32 mma, online softmax) ----------------
// Grid: (L/128, B*H). 128 threads = 4 warps, each warp owns 32 query rows
// (two m16 tiles) so every K/V fragment read from SMEM feeds two MMAs.
// K tiles use stride 68 (4g+t bank-spread), V tiles stride 72 (8t+g spread).
// 3-stage cp.async pipeline; P stays in registers (shuffle redistribution).
#define BLKQ 128
#define BLKK 64
#define KLDK 68      // K tile row stride (floats)
#define KLDV 72      // V tile row stride (floats)
#define NSTAGE 3
#define KTILE (BLKK * KLDK)
#define VTILE (BLKK * KLDV)

__global__ __launch_bounds__(128)
void attn_kernel(const int* __restrict__ mask)
{
    extern __shared__ float sm[];
    float* Ks  = sm;                                    // NSTAGE x KTILE
    float* Vs  = sm + NSTAGE * KTILE;                   // NSTAGE x VTILE
    int*   mbs = (int*)(sm + NSTAGE * (KTILE + VTILE)); // NSTAGE x BLKK

    const int tid  = threadIdx.x;
    const int lane = tid & 31;
    const int w    = tid >> 5;            // 0..3
    const int g    = lane >> 2;
    const int t    = lane & 3;
    const int bh   = blockIdx.y;          // 0..31
    const int b    = bh >> 4;             // batch
    const int q0   = blockIdx.x * BLKQ;
    const size_t base = (size_t)bh * LSEQ * HDIM;

    // --- cp.async tile issue: K + V (64x64 f32 each) + 64 mask ints ---
    auto issue_tile = [&](int kt) {
        int st = kt % NSTAGE;
        const float* Kp = g_K + base + (size_t)kt * BLKK * HDIM;
        const float* Vp = g_V + base + (size_t)kt * BLKK * HDIM;
        float* Kd = Ks + st * KTILE;
        float* Vd = Vs + st * VTILE;
        #pragma unroll
        for (int it = 0; it < 8; ++it) {
            int i = tid + it * 128;            // 0..1023 16B chunks
            int r = i >> 4, c = (i & 15) * 4;
            cpa16(Kd + r * KLDK + c, Kp + r * HDIM + c);
            cpa16(Vd + r * KLDV + c, Vp + r * HDIM + c);
        }
        if (tid < BLKK / 4)
            cpa16(mbs + st * BLKK + tid * 4, mask + b * LSEQ + kt * BLKK + tid * 4);
        cp_commit();
    };

    // preload Q fragments for both m16 tiles (rows w*32 + mt*16 + {g, g+8})
    uint32_t qf[2][8][4];
    #pragma unroll
    for (int mt = 0; mt < 2; mt++) {
        const int r = q0 + w * 32 + mt * 16 + g;
        const float* Qp = g_Q + base + (size_t)r * HDIM;
        #pragma unroll
        for (int kk = 0; kk < 8; kk++) {
            int c = kk * 8 + t;
            qf[mt][kk][0] = __float_as_uint(Qp[c]);
            qf[mt][kk][1] = __float_as_uint(Qp[8 * HDIM + c]);
            qf[mt][kk][2] = __float_as_uint(Qp[c + 4]);
            qf[mt][kk][3] = __float_as_uint(Qp[8 * HDIM + c + 4]);
        }
    }

    float o[2][8][4];
    #pragma unroll
    for (int mt = 0; mt < 2; mt++)
        #pragma unroll
        for (int nt = 0; nt < 8; nt++)
            #pragma unroll
            for (int e = 0; e < 4; e++) o[mt][nt][e] = 0.f;
    float mrow[2][2] = {{-1e30f, -1e30f}, {-1e30f, -1e30f}};
    float lrow[2][2] = {{0.f, 0.f}, {0.f, 0.f}};

    const int NT = LSEQ / BLKK;            // 32
    issue_tile(0);
    issue_tile(1);

    const int srcA = (lane & 28) | (t >> 1);  // owner of col t
    const int srcB = srcA | 2;                // owner of col t+4
    const bool odd = (t & 1);

    for (int kt = 0; kt < NT; ++kt) {
        if (kt + 1 < NT) cp_wait<1>(); else cp_wait<0>();
        __syncthreads();                   // tile kt ready; stage (kt+2)%3 free
        if (kt + 2 < NT) issue_tile(kt + 2);

        const int st = kt % NSTAGE;
        const float* Ksb = Ks + st * KTILE;
        const float* Vsb = Vs + st * VTILE;
        const int*   mbb = mbs + st * BLKK;

        // S = Q K^T : each K fragment feeds both m-tiles
        float s[2][8][4];
        #pragma unroll
        for (int mt = 0; mt < 2; mt++)
            #pragma unroll
            for (int nt = 0; nt < 8; nt++)
                #pragma unroll
                for (int e = 0; e < 4; e++) s[mt][nt][e] = 0.f;
        #pragma unroll
        for (int kk = 0; kk < 8; kk++) {
            uint32_t bf[8][2];
            #pragma unroll
            for (int nt = 0; nt < 8; nt++) {
                bf[nt][0] = __float_as_uint(Ksb[(nt * 8 + g) * KLDK + kk * 8 + t]);
                bf[nt][1] = __float_as_uint(Ksb[(nt * 8 + g) * KLDK + kk * 8 + t + 4]);
            }
            #pragma unroll
            for (int mt = 0; mt < 2; mt++)
                #pragma unroll
                for (int nt = 0; nt < 8; nt++)
                    mma8(s[mt][nt], qf[mt][kk], bf[nt]);
        }

        // softmax (per m-tile): scale + mask + online max/sum; P tf32-rounded
        #pragma unroll
        for (int mt = 0; mt < 2; mt++) {
            float mx0 = -1e30f, mx1 = -1e30f;
            #pragma unroll
            for (int nt = 0; nt < 8; nt++) {
                float b0 = mbb[nt * 8 + 2 * t]     ? 0.f : -1e30f;
                float b1 = mbb[nt * 8 + 2 * t + 1] ? 0.f : -1e30f;
                s[mt][nt][0] = s[mt][nt][0] * 0.125f + b0;
                s[mt][nt][1] = s[mt][nt][1] * 0.125f + b1;
                s[mt][nt][2] = s[mt][nt][2] * 0.125f + b0;
                s[mt][nt][3] = s[mt][nt][3] * 0.125f + b1;
                mx0 = fmaxf(mx0, fmaxf(s[mt][nt][0], s[mt][nt][1]));
                mx1 = fmaxf(mx1, fmaxf(s[mt][nt][2], s[mt][nt][3]));
            }
            mx0 = fmaxf(mx0, __shfl_xor_sync(0xffffffffu, mx0, 1));
            mx0 = fmaxf(mx0, __shfl_xor_sync(0xffffffffu, mx0, 2));
            mx1 = fmaxf(mx1, __shfl_xor_sync(0xffffffffu, mx1, 1));
            mx1 = fmaxf(mx1, __shfl_xor_sync(0xffffffffu, mx1, 2));

            float mn0 = fmaxf(mrow[mt][0], mx0), mn1 = fmaxf(mrow[mt][1], mx1);
            float e0 = __expf(mrow[mt][0] - mn0), e1 = __expf(mrow[mt][1] - mn1);
            mrow[mt][0] = mn0; mrow[mt][1] = mn1;
            float ps0 = 0.f, ps1 = 0.f;
            #pragma unroll
            for (int nt = 0; nt < 8; nt++) {
                o[mt][nt][0] *= e0; o[mt][nt][1] *= e0;
                o[mt][nt][2] *= e1; o[mt][nt][3] *= e1;
                s[mt][nt][0] = f2tff(__expf(s[mt][nt][0] - mn0));
                s[mt][nt][1] = f2tff(__expf(s[mt][nt][1] - mn0));
                s[mt][nt][2] = f2tff(__expf(s[mt][nt][2] - mn1));
                s[mt][nt][3] = f2tff(__expf(s[mt][nt][3] - mn1));
                ps0 += s[mt][nt][0] + s[mt][nt][1];
                ps1 += s[mt][nt][2] + s[mt][nt][3];
            }
            ps0 += __shfl_xor_sync(0xffffffffu, ps0, 1);
            ps0 += __shfl_xor_sync(0xffffffffu, ps0, 2);
            ps1 += __shfl_xor_sync(0xffffffffu, ps1, 1);
            ps1 += __shfl_xor_sync(0xffffffffu, ps1, 2);
            lrow[mt][0] = lrow[mt][0] * e0 + ps0;
            lrow[mt][1] = lrow[mt][1] * e1 + ps1;
        }

        // O += P V : each V fragment feeds both m-tiles; P redistributed from
        // accumulator layout (cols 2t,2t+1) to A-operand layout via shuffles.
        #pragma unroll
        for (int kk = 0; kk < 8; kk++) {
            uint32_t bfv[8][2];
            #pragma unroll
            for (int nt = 0; nt < 8; nt++) {
                bfv[nt][0] = __float_as_uint(Vsb[(kk * 8 + t) * KLDV + nt * 8 + g]);
                bfv[nt][1] = __float_as_uint(Vsb[(kk * 8 + t + 4) * KLDV + nt * 8 + g]);
            }
            #pragma unroll
            for (int mt = 0; mt < 2; mt++) {
                float x0 = __shfl_sync(0xffffffffu, s[mt][kk][0], srcA);
                float x1 = __shfl_sync(0xffffffffu, s[mt][kk][1], srcA);
                float x2 = __shfl_sync(0xffffffffu, s[mt][kk][2], srcA);
                float x3 = __shfl_sync(0xffffffffu, s[mt][kk][3], srcA);
                float y0 = __shfl_sync(0xffffffffu, s[mt][kk][0], srcB);
                float y1 = __shfl_sync(0xffffffffu, s[mt][kk][1], srcB);
                float y2 = __shfl_sync(0xffffffffu, s[mt][kk][2], srcB);
                float y3 = __shfl_sync(0xffffffffu, s[mt][kk][3], srcB);
                uint32_t af[4];
                af[0] = __float_as_uint(odd ? x1 : x0);   // P[g   ][kk*8+t]
                af[1] = __float_as_uint(odd ? x3 : x2);   // P[g+8 ][kk*8+t]
                af[2] = __float_as_uint(odd ? y1 : y0);   // P[g   ][kk*8+t+4]
                af[3] = __float_as_uint(odd ? y3 : y2);   // P[g+8 ][kk*8+t+4]
                #pragma unroll
                for (int nt = 0; nt < 8; nt++)
                    mma8(o[mt][nt], af, bfv[nt]);
            }
        }
    }

    // epilogue: normalize; fully-masked rows -> 0 (matches NaN->0 reference).
    // Store tf32-rounded so gemm_out consumes raw bytes (same rounding point
    // as the previous per-fragment cvt -> bit-identical).
    #pragma unroll
    for (int mt = 0; mt < 2; mt++) {
        float inv0 = (mrow[mt][0] > -1e29f) ? (1.f / lrow[mt][0]) : 0.f;
        float inv1 = (mrow[mt][1] > -1e29f) ? (1.f / lrow[mt][1]) : 0.f;
        const int r = q0 + w * 32 + mt * 16 + g;
        float* Cp = g_C + base + (size_t)r * HDIM;
        #pragma unroll
        for (int nt = 0; nt < 8; nt++) {
            int c = nt * 8 + 2 * t;
            Cp[c]                = f2tff(o[mt][nt][0] * inv0);
            Cp[c + 1]            = f2tff(o[mt][nt][1] * inv0);
            Cp[8 * HDIM + c]     = f2tff(o[mt][nt][2] * inv1);
            Cp[8 * HDIM + c + 1] = f2tff(o[mt][nt][3] * inv1);
        }
    }
}

// ---------------- launcher ---------------------------------------------------
extern "C" void kernel_launch(void* const* d_in, const int* in_sizes, int n_in,
                              void* d_out, int out_size)
{
    const float* query = (const float*)d_in[0];
    const float* key   = (const float*)d_in[1];
    const float* value = (const float*)d_in[2];
    const int*   mask  = (const int*)d_in[3];
    const float* Wq    = (const float*)d_in[4];
    const float* Wk    = (const float*)d_in[5];
    const float* Wv    = (const float*)d_in[6];
    const float* Wo    = (const float*)d_in[7];
    const float* bo    = (const float*)d_in[8];
    float* out = (float*)d_out;

    float *pQ, *pK, *pV, *pC;
    cudaGetSymbolAddress((void**)&pQ, g_Q);
    cudaGetSymbolAddress((void**)&pK, g_K);
    cudaGetSymbolAddress((void**)&pV, g_V);
    cudaGetSymbolAddress((void**)&pC, g_C);

    // 1) round inputs + weights to tf32 once (bit-identical hoist of the cvts)
    round_pass<<<dim3(MROWS * D_MODEL / 4 / 256, 7), 256>>>(
        query, key, value, Wq, Wk, Wv, Wo);

    const int gemm_smem = GSTG * (GA_TILE + GB_TILE) * (int)sizeof(float); // 60KB
    cudaFuncSetAttribute(gemm_qkv, cudaFuncAttributeMaxDynamicSharedMemorySize, gemm_smem);
    cudaFuncSetAttribute(gemm_out, cudaFuncAttributeMaxDynamicSharedMemorySize, gemm_smem);

    // 2) fused QKV projections
    dim3 gq(D_MODEL / GN, MROWS / GM, 3);   // (8, 32, 3)
    gemm_qkv<<<gq, 256, gemm_smem>>>(pQ, pK, pV);

    // 3) attention
    const int attn_smem = NSTAGE * (KTILE + VTILE) * (int)sizeof(float)
                        + NSTAGE * BLKK * (int)sizeof(int);
    cudaFuncSetAttribute(attn_kernel, cudaFuncAttributeMaxDynamicSharedMemorySize, attn_smem);
    attn_kernel<<<dim3(LSEQ / BLKQ, BB * NHEAD), 128, attn_smem>>>(mask);

    // 4) output projection
    dim3 gg(D_MODEL / GN, MROWS / GM);      // (8, 32)
    gemm_out<<<gg, 256, gemm_smem>>>(pC, bo, out);
}

// round 17
// speedup vs baseline: 1.0621x; 1.0621x over previous
#include <cuda_runtime.h>
#include <cstdint>

// Problem constants
#define D_MODEL 1024
#define NHEAD   16
#define HDIM    64
#define BB      2
#define LSEQ    2048
#define MROWS   (BB * LSEQ)   // 4096

// ---------------- scratch (device globals; no allocations allowed) ----------
__device__ float g_Q[MROWS * D_MODEL];   // head-major (B,H,L,HDIM), tf32-rounded
__device__ float g_K[MROWS * D_MODEL];
__device__ float g_V[MROWS * D_MODEL];
__device__ float g_C[MROWS * D_MODEL];   // attention context, head-major

// ---------------- helpers ---------------------------------------------------
__device__ __forceinline__ uint32_t f2tf(float x) {
    uint32_t r;
    asm("cvt.rna.tf32.f32 %0, %1;" : "=r"(r) : "f"(x));
    return r;
}
__device__ __forceinline__ float f2tff(float x) { return __uint_as_float(f2tf(x)); }

__device__ __forceinline__ void mma8(float* c, const uint32_t* a, const uint32_t* b) {
    asm volatile(
        "mma.sync.aligned.m16n8k8.row.col.f32.tf32.tf32.f32 "
        "{%0,%1,%2,%3},{%4,%5,%6,%7},{%8,%9},{%0,%1,%2,%3};\n"
        : "+f"(c[0]), "+f"(c[1]), "+f"(c[2]), "+f"(c[3])
        : "r"(a[0]), "r"(a[1]), "r"(a[2]), "r"(a[3]), "r"(b[0]), "r"(b[1]));
}

__device__ __forceinline__ void cpa16(void* dst, const void* src) {
    uint32_t d = (uint32_t)__cvta_generic_to_shared(dst);
    asm volatile("cp.async.cg.shared.global [%0], [%1], 16;" :: "r"(d), "l"(src));
}
__device__ __forceinline__ void cp_commit() {
    asm volatile("cp.async.commit_group;");
}
template<int N>
__device__ __forceinline__ void cp_wait() {
    asm volatile("cp.async.wait_group %0;" :: "n"(N));
}

// ---------------- TF32 GEMM body: C[M,N] = A[M,K] * W[N,K]^T (+bias) --------
// M=4096, N=K=1024. Block tile 128x128, BK=32 (double-buffered, 2 stages),
// 256 threads = 8 warps, each warp owns a 64x32 tile. Deep K-slab halves the
// number of __syncthreads/cp-wait serialization points (32 vs 64) so each
// barrier amortizes over 64 MMAs/warp. 72KB SMEM -> 2 CTAs/SM. tf32 RNA
// rounding applied on fragments right before the MMA (R14 showed the cvts
// are latency-hidden and free).
#define GM   128
#define GN   128
#define GK   32
#define GLD  36     // padded row stride (floats); g*36+t mod 32 distinct
#define GSTG 2
#define GA_TILE (GM * GLD)
#define GB_TILE (GN * GLD)

template<bool A_HEADED, bool OUT_HEADED, bool HAS_BIAS>
__device__ __forceinline__
void gemm_body(const float* __restrict__ A, const float* __restrict__ W,
               const float* __restrict__ bias, float* __restrict__ C)
{
    extern __shared__ float gsm[];
    float* As = gsm;                    // GSTG x GA_TILE
    float* Bs = gsm + GSTG * GA_TILE;   // GSTG x GB_TILE

    const int tid  = threadIdx.x;
    const int m0   = blockIdx.y * GM;
    const int n0   = blockIdx.x * GN;
    const int lane = tid & 31;
    const int wid  = tid >> 5;
    const int g    = lane >> 2;       // groupID
    const int t    = lane & 3;        // threadID_in_group
    const int wm   = (wid & 1) * 64;  // warp m offset (2-way)
    const int wn   = (wid >> 1) * 32; // warp n offset (4-way)

    auto a_ptr = [&](int m, int k) -> const float* {
        if (A_HEADED) {
            int b = m >> 11, l = m & (LSEQ - 1);
            int h = k >> 6,  d = k & (HDIM - 1);
            return A + (((size_t)(b * NHEAD + h) * LSEQ + l) * HDIM + d);
        } else {
            return A + (size_t)m * D_MODEL + k;
        }
    };

    // stage kt-th K-slab: A 128x32 (1024 16B chunks) + B 128x32 (1024 chunks)
    auto issue_tile = [&](int kt) {
        const int st = kt & 1;
        const int k0 = kt * GK;
        float* Ad = As + st * GA_TILE;
        float* Bd = Bs + st * GB_TILE;
        #pragma unroll
        for (int it = 0; it < 4; ++it) {
            int i = tid + it * 256;           // 0..1023
            int r = i >> 3, c = (i & 7) * 4;
            cpa16(Ad + r * GLD + c, a_ptr(m0 + r, k0 + c));
        }
        #pragma unroll
        for (int it = 0; it < 4; ++it) {
            int i = tid + it * 256;           // 0..1023
            int r = i >> 3, c = (i & 7) * 4;
            cpa16(Bd + r * GLD + c, W + (size_t)(n0 + r) * D_MODEL + k0 + c);
        }
        cp_commit();
    };

    float acc[4][4][4];
    #pragma unroll
    for (int i = 0; i < 4; i++)
        #pragma unroll
        for (int j = 0; j < 4; j++)
            #pragma unroll
            for (int e = 0; e < 4; e++) acc[i][j][e] = 0.f;

    const int NKT = D_MODEL / GK;   // 32
    issue_tile(0);

    for (int kt = 0; kt < NKT; ++kt) {
        cp_wait<0>();                 // only group kt is pending here
        __syncthreads();              // stage kt ready; other stage now free
        if (kt + 1 < NKT) issue_tile(kt + 1);  // overlaps compute(kt)

        const int st = kt & 1;
        const float* Asb = As + st * GA_TILE;
        const float* Bsb = Bs + st * GB_TILE;

        #pragma unroll
        for (int kk = 0; kk < GK; kk += 8) {
            uint32_t af[4][4];
            #pragma unroll
            for (int mt = 0; mt < 4; mt++) {
                int r = wm + mt * 16 + g;
                af[mt][0] = f2tf(Asb[r * GLD + kk + t]);
                af[mt][1] = f2tf(Asb[(r + 8) * GLD + kk + t]);
                af[mt][2] = f2tf(Asb[r * GLD + kk + t + 4]);
                af[mt][3] = f2tf(Asb[(r + 8) * GLD + kk + t + 4]);
            }
            uint32_t bf[4][2];
            #pragma unroll
            for (int nt = 0; nt < 4; nt++) {
                int n = wn + nt * 8 + g;
                bf[nt][0] = f2tf(Bsb[n * GLD + kk + t]);
                bf[nt][1] = f2tf(Bsb[n * GLD + kk + t + 4]);
            }
            #pragma unroll
            for (int mt = 0; mt < 4; mt++)
                #pragma unroll
                for (int nt = 0; nt < 4; nt++)
                    mma8(acc[mt][nt], af[mt], bf[nt]);
        }
        __syncthreads();              // compute(kt) done before stage reuse
    }

    // epilogue
    #pragma unroll
    for (int mt = 0; mt < 4; mt++) {
        #pragma unroll
        for (int nt = 0; nt < 4; nt++) {
            int m = m0 + wm + mt * 16 + g;
            int n = n0 + wn + nt * 8 + 2 * t;
            float v0 = acc[mt][nt][0], v1 = acc[mt][nt][1];
            float v2 = acc[mt][nt][2], v3 = acc[mt][nt][3];
            if (HAS_BIAS) {
                float b0 = bias[n], b1 = bias[n + 1];
                v0 += b0; v1 += b1; v2 += b0; v3 += b1;
            }
            if (OUT_HEADED) {
                // round to tf32 here so attention can consume raw bytes
                v0 = f2tff(v0); v1 = f2tff(v1); v2 = f2tff(v2); v3 = f2tff(v3);
                int b = m >> 11, l = m & (LSEQ - 1);
                int h = n >> 6,  d = n & (HDIM - 1);
                size_t base = ((size_t)(b * NHEAD + h) * LSEQ + l) * HDIM + d;
                size_t base8 = base + 8 * HDIM;
                C[base]     = v0; C[base + 1]  = v1;
                C[base8]    = v2; C[base8 + 1] = v3;
            } else {
                C[(size_t)m * D_MODEL + n]           = v0;
                C[(size_t)m * D_MODEL + n + 1]       = v1;
                C[(size_t)(m + 8) * D_MODEL + n]     = v2;
                C[(size_t)(m + 8) * D_MODEL + n + 1] = v3;
            }
        }
    }
}

// fused QKV projections: blockIdx.z selects {query,key,value}
__global__ __launch_bounds__(256, 2)
void gemm_qkv(const float* __restrict__ q, const float* __restrict__ k,
              const float* __restrict__ v,
              const float* __restrict__ Wq, const float* __restrict__ Wk,
              const float* __restrict__ Wv,
              float* __restrict__ pQ, float* __restrict__ pK, float* __restrict__ pV)
{
    const int z = blockIdx.z;
    const float* A = (z == 0) ? q : (z == 1) ? k : v;
    const float* W = (z == 0) ? Wq : (z == 1) ? Wk : Wv;
    float*       C = (z == 0) ? pQ : (z == 1) ? pK : pV;
    gemm_body<false, true, false>(A, W, nullptr, C);
}

// output projection
__global__ __launch_bounds__(256, 2)
void gemm_out(const float* __restrict__ A, const float* __restrict__ W,
              const float* __restrict__ bias, float* __restrict__ C)
{
    gemm_body<true, false, true>(A, W, bias, C);
}

// ---------------- flash attention (TF32 mma, online softmax) ----------------
// Grid: (L/128, B*H). 128 threads = 4 warps, each warp owns 32 query rows
// (two m16 tiles) so every K/V fragment read from SMEM feeds two MMAs.
// K tiles use stride 68 (4g+t bank-spread), V tiles stride 72 (8t+g spread).
// 3-stage cp.async pipeline; P stays in registers (shuffle redistribution).
#define BLKQ 128
#define BLKK 64
#define KLDK 68      // K tile row stride (floats)
#define KLDV 72      // V tile row stride (floats)
#define NSTAGE 3
#define KTILE (BLKK * KLDK)
#define VTILE (BLKK * KLDV)

__global__ __launch_bounds__(128)
void attn_kernel(const int* __restrict__ mask)
{
    extern __shared__ float sm[];
    float* Ks  = sm;                                    // NSTAGE x KTILE
    float* Vs  = sm + NSTAGE * KTILE;                   // NSTAGE x VTILE
    int*   mbs = (int*)(sm + NSTAGE * (KTILE + VTILE)); // NSTAGE x BLKK

    const int tid  = threadIdx.x;
    const int lane = tid & 31;
    const int w    = tid >> 5;            // 0..3
    const int g    = lane >> 2;
    const int t    = lane & 3;
    const int bh   = blockIdx.y;          // 0..31
    const int b    = bh >> 4;             // batch
    const int q0   = blockIdx.x * BLKQ;
    const size_t base = (size_t)bh * LSEQ * HDIM;

    // --- cp.async tile issue: K + V (64x64 f32 each) + 64 mask ints ---
    auto issue_tile = [&](int kt) {
        int st = kt % NSTAGE;
        const float* Kp = g_K + base + (size_t)kt * BLKK * HDIM;
        const float* Vp = g_V + base + (size_t)kt * BLKK * HDIM;
        float* Kd = Ks + st * KTILE;
        float* Vd = Vs + st * VTILE;
        #pragma unroll
        for (int it = 0; it < 8; ++it) {
            int i = tid + it * 128;            // 0..1023 16B chunks
            int r = i >> 4, c = (i & 15) * 4;
            cpa16(Kd + r * KLDK + c, Kp + r * HDIM + c);
            cpa16(Vd + r * KLDV + c, Vp + r * HDIM + c);
        }
        if (tid < BLKK / 4)
            cpa16(mbs + st * BLKK + tid * 4, mask + b * LSEQ + kt * BLKK + tid * 4);
        cp_commit();
    };

    // preload Q fragments for both m16 tiles (rows w*32 + mt*16 + {g, g+8})
    uint32_t qf[2][8][4];
    #pragma unroll
    for (int mt = 0; mt < 2; mt++) {
        const int r = q0 + w * 32 + mt * 16 + g;
        const float* Qp = g_Q + base + (size_t)r * HDIM;
        #pragma unroll
        for (int kk = 0; kk < 8; kk++) {
            int c = kk * 8 + t;
            qf[mt][kk][0] = __float_as_uint(Qp[c]);
            qf[mt][kk][1] = __float_as_uint(Qp[8 * HDIM + c]);
            qf[mt][kk][2] = __float_as_uint(Qp[c + 4]);
            qf[mt][kk][3] = __float_as_uint(Qp[8 * HDIM + c + 4]);
        }
    }

    float o[2][8][4];
    #pragma unroll
    for (int mt = 0; mt < 2; mt++)
        #pragma unroll
        for (int nt = 0; nt < 8; nt++)
            #pragma unroll
            for (int e = 0; e < 4; e++) o[mt][nt][e] = 0.f;
    float mrow[2][2] = {{-1e30f, -1e30f}, {-1e30f, -1e30f}};
    float lrow[2][2] = {{0.f, 0.f}, {0.f, 0.f}};

    const int NT = LSEQ / BLKK;            // 32
    issue_tile(0);
    issue_tile(1);

    const int srcA = (lane & 28) | (t >> 1);  // owner of col t
    const int srcB = srcA | 2;                // owner of col t+4
    const bool odd = (t & 1);

    for (int kt = 0; kt < NT; ++kt) {
        if (kt + 1 < NT) cp_wait<1>(); else cp_wait<0>();
        __syncthreads();                   // tile kt ready; stage (kt+2)%3 free
        if (kt + 2 < NT) issue_tile(kt + 2);

        const int st = kt % NSTAGE;
        const float* Ksb = Ks + st * KTILE;
        const float* Vsb = Vs + st * VTILE;
        const int*   mbb = mbs + st * BLKK;

        // S = Q K^T : each K fragment feeds both m-tiles
        float s[2][8][4];
        #pragma unroll
        for (int mt = 0; mt < 2; mt++)
            #pragma unroll
            for (int nt = 0; nt < 8; nt++)
                #pragma unroll
                for (int e = 0; e < 4; e++) s[mt][nt][e] = 0.f;
        #pragma unroll
        for (int kk = 0; kk < 8; kk++) {
            uint32_t bf[8][2];
            #pragma unroll
            for (int nt = 0; nt < 8; nt++) {
                bf[nt][0] = __float_as_uint(Ksb[(nt * 8 + g) * KLDK + kk * 8 + t]);
                bf[nt][1] = __float_as_uint(Ksb[(nt * 8 + g) * KLDK + kk * 8 + t + 4]);
            }
            #pragma unroll
            for (int mt = 0; mt < 2; mt++)
                #pragma unroll
                for (int nt = 0; nt < 8; nt++)
                    mma8(s[mt][nt], qf[mt][kk], bf[nt]);
        }

        // softmax (per m-tile): scale + mask + online max/sum; P tf32-rounded
        #pragma unroll
        for (int mt = 0; mt < 2; mt++) {
            float mx0 = -1e30f, mx1 = -1e30f;
            #pragma unroll
            for (int nt = 0; nt < 8; nt++) {
                float b0 = mbb[nt * 8 + 2 * t]     ? 0.f : -1e30f;
                float b1 = mbb[nt * 8 + 2 * t + 1] ? 0.f : -1e30f;
                s[mt][nt][0] = s[mt][nt][0] * 0.125f + b0;
                s[mt][nt][1] = s[mt][nt][1] * 0.125f + b1;
                s[mt][nt][2] = s[mt][nt][2] * 0.125f + b0;
                s[mt][nt][3] = s[mt][nt][3] * 0.125f + b1;
                mx0 = fmaxf(mx0, fmaxf(s[mt][nt][0], s[mt][nt][1]));
                mx1 = fmaxf(mx1, fmaxf(s[mt][nt][2], s[mt][nt][3]));
            }
            mx0 = fmaxf(mx0, __shfl_xor_sync(0xffffffffu, mx0, 1));
            mx0 = fmaxf(mx0, __shfl_xor_sync(0xffffffffu, mx0, 2));
            mx1 = fmaxf(mx1, __shfl_xor_sync(0xffffffffu, mx1, 1));
            mx1 = fmaxf(mx1, __shfl_xor_sync(0xffffffffu, mx1, 2));

            float mn0 = fmaxf(mrow[mt][0], mx0), mn1 = fmaxf(mrow[mt][1], mx1);
            float e0 = __expf(mrow[mt][0] - mn0), e1 = __expf(mrow[mt][1] - mn1);
            mrow[mt][0] = mn0; mrow[mt][1] = mn1;
            float ps0 = 0.f, ps1 = 0.f;
            #pragma unroll
            for (int nt = 0; nt < 8; nt++) {
                o[mt][nt][0] *= e0; o[mt][nt][1] *= e0;
                o[mt][nt][2] *= e1; o[mt][nt][3] *= e1;
                s[mt][nt][0] = f2tff(__expf(s[mt][nt][0] - mn0));
                s[mt][nt][1] = f2tff(__expf(s[mt][nt][1] - mn0));
                s[mt][nt][2] = f2tff(__expf(s[mt][nt][2] - mn1));
                s[mt][nt][3] = f2tff(__expf(s[mt][nt][3] - mn1));
                ps0 += s[mt][nt][0] + s[mt][nt][1];
                ps1 += s[mt][nt][2] + s[mt][nt][3];
            }
            ps0 += __shfl_xor_sync(0xffffffffu, ps0, 1);
            ps0 += __shfl_xor_sync(0xffffffffu, ps0, 2);
            ps1 += __shfl_xor_sync(0xffffffffu, ps1, 1);
            ps1 += __shfl_xor_sync(0xffffffffu, ps1, 2);
            lrow[mt][0] = lrow[mt][0] * e0 + ps0;
            lrow[mt][1] = lrow[mt][1] * e1 + ps1;
        }

        // O += P V : each V fragment feeds both m-tiles; P redistributed from
        // accumulator layout (cols 2t,2t+1) to A-operand layout via shuffles.
        #pragma unroll
        for (int kk = 0; kk < 8; kk++) {
            uint32_t bfv[8][2];
            #pragma unroll
            for (int nt = 0; nt < 8; nt++) {
                bfv[nt][0] = __float_as_uint(Vsb[(kk * 8 + t) * KLDV + nt * 8 + g]);
                bfv[nt][1] = __float_as_uint(Vsb[(kk * 8 + t + 4) * KLDV + nt * 8 + g]);
            }
            #pragma unroll
            for (int mt = 0; mt < 2; mt++) {
                float x0 = __shfl_sync(0xffffffffu, s[mt][kk][0], srcA);
                float x1 = __shfl_sync(0xffffffffu, s[mt][kk][1], srcA);
                float x2 = __shfl_sync(0xffffffffu, s[mt][kk][2], srcA);
                float x3 = __shfl_sync(0xffffffffu, s[mt][kk][3], srcA);
                float y0 = __shfl_sync(0xffffffffu, s[mt][kk][0], srcB);
                float y1 = __shfl_sync(0xffffffffu, s[mt][kk][1], srcB);
                float y2 = __shfl_sync(0xffffffffu, s[mt][kk][2], srcB);
                float y3 = __shfl_sync(0xffffffffu, s[mt][kk][3], srcB);
                uint32_t af[4];
                af[0] = __float_as_uint(odd ? x1 : x0);   // P[g   ][kk*8+t]
                af[1] = __float_as_uint(odd ? x3 : x2);   // P[g+8 ][kk*8+t]
                af[2] = __float_as_uint(odd ? y1 : y0);   // P[g   ][kk*8+t+4]
                af[3] = __float_as_uint(odd ? y3 : y2);   // P[g+8 ][kk*8+t+4]
                #pragma unroll
                for (int nt = 0; nt < 8; nt++)
                    mma8(o[mt][nt], af, bfv[nt]);
            }
        }
    }

    // epilogue: normalize; fully-masked rows -> 0 (matches NaN->0 reference)
    #pragma unroll
    for (int mt = 0; mt < 2; mt++) {
        float inv0 = (mrow[mt][0] > -1e29f) ? (1.f / lrow[mt][0]) : 0.f;
        float inv1 = (mrow[mt][1] > -1e29f) ? (1.f / lrow[mt][1]) : 0.f;
        const int r = q0 + w * 32 + mt * 16 + g;
        float* Cp = g_C + base + (size_t)r * HDIM;
        #pragma unroll
        for (int nt = 0; nt < 8; nt++) {
            int c = nt * 8 + 2 * t;
            Cp[c]                = o[mt][nt][0] * inv0;
            Cp[c + 1]            = o[mt][nt][1] * inv0;
            Cp[8 * HDIM + c]     = o[mt][nt][2] * inv1;
            Cp[8 * HDIM + c + 1] = o[mt][nt][3] * inv1;
        }
    }
}

// ---------------- launcher ---------------------------------------------------
extern "C" void kernel_launch(void* const* d_in, const int* in_sizes, int n_in,
                              void* d_out, int out_size)
{
    const float* query = (const float*)d_in[0];
    const float* key   = (const float*)d_in[1];
    const float* value = (const float*)d_in[2];
    const int*   mask  = (const int*)d_in[3];
    const float* Wq    = (const float*)d_in[4];
    const float* Wk    = (const float*)d_in[5];
    const float* Wv    = (const float*)d_in[6];
    const float* Wo    = (const float*)d_in[7];
    const float* bo    = (const float*)d_in[8];
    float* out = (float*)d_out;

    float *pQ, *pK, *pV, *pC;
    cudaGetSymbolAddress((void**)&pQ, g_Q);
    cudaGetSymbolAddress((void**)&pK, g_K);
    cudaGetSymbolAddress((void**)&pV, g_V);
    cudaGetSymbolAddress((void**)&pC, g_C);

    const int gemm_smem = GSTG * (GA_TILE + GB_TILE) * (int)sizeof(float); // 72KB
    cudaFuncSetAttribute(gemm_qkv, cudaFuncAttributeMaxDynamicSharedMemorySize, gemm_smem);
    cudaFuncSetAttribute(gemm_out, cudaFuncAttributeMaxDynamicSharedMemorySize, gemm_smem);

    dim3 gq(D_MODEL / GN, MROWS / GM, 3);   // (8, 32, 3) fused QKV
    gemm_qkv<<<gq, 256, gemm_smem>>>(query, key, value, Wq, Wk, Wv, pQ, pK, pV);

    const int attn_smem = NSTAGE * (KTILE + VTILE) * (int)sizeof(float)
                        + NSTAGE * BLKK * (int)sizeof(int);
    cudaFuncSetAttribute(attn_kernel, cudaFuncAttributeMaxDynamicSharedMemorySize, attn_smem);
    attn_kernel<<<dim3(LSEQ / BLKQ, BB * NHEAD), 128, attn_smem>>>(mask);

    dim3 gg(D_MODEL / GN, MROWS / GM);      // (8, 32)
    gemm_out<<<gg, 256, gemm_smem>>>(pC, Wo, bo, out);
}